// round 7
// baseline (speedup 1.0000x reference)
#include <cuda_runtime.h>
#include <cuda_bf16.h>

// Problem constants
// T=1024, B=4, E=512, H=8, HD=64, BH=32
// inputs: query[T,B,E], dist[B,T,T,H], in_proj_weight[3E,E], in_proj_bias[3E],
//         out_proj_weight[E,E], out_proj_bias[E]
// output: [T,B,E] float32

namespace {
constexpr int cT  = 1024;
constexpr int cB  = 4;
constexpr int cE  = 512;
constexpr int cH  = 8;
constexpr int cHD = 64;
constexpr int cBH = cB * cH;   // 32
}

// Scratch (no allocation allowed -> device globals)
__device__ float g_q[cBH * cT * cHD];                 // 8 MB, pre-scaled by 1/sqrt(HD)
__device__ float g_k[cBH * cT * cHD];                 // 8 MB
__device__ float g_v[cBH * cT * cHD];                 // 8 MB
__device__ float g_ctx[cT * cB * cE];                 // 8 MB attention output in [T,B,E]

// ---------------------------------------------------------------------------
// Kernel 1: in-projection GEMM. M=4096 (t*B+b), N=1536, K=512 (NT, both K-major)
// Epilogue scatters into q/k/v head layout [BH][T][HD]; q scaled by 0.125.
// ---------------------------------------------------------------------------
__global__ __launch_bounds__(256) void k_inproj(const float* __restrict__ A,
                                                const float* __restrict__ W,
                                                const float* __restrict__ bias) {
    __shared__ float As[8][128];
    __shared__ float Bs[8][128];
    const int tid = threadIdx.x;
    const int tx = tid & 15, ty = tid >> 4;
    const int m0 = blockIdx.y * 128, n0 = blockIdx.x * 128;
    const int lrow = tid >> 1, lcol = (tid & 1) << 2;

    float acc[8][8];
#pragma unroll
    for (int i = 0; i < 8; i++)
#pragma unroll
        for (int j = 0; j < 8; j++) acc[i][j] = 0.f;

    const float* aptr = A + (m0 + lrow) * 512 + lcol;
    const float* bptr = W + (n0 + lrow) * 512 + lcol;

    for (int k0 = 0; k0 < 512; k0 += 8) {
        float4 av = *reinterpret_cast<const float4*>(aptr + k0);
        float4 bv = *reinterpret_cast<const float4*>(bptr + k0);
        As[lcol + 0][lrow] = av.x; As[lcol + 1][lrow] = av.y;
        As[lcol + 2][lrow] = av.z; As[lcol + 3][lrow] = av.w;
        Bs[lcol + 0][lrow] = bv.x; Bs[lcol + 1][lrow] = bv.y;
        Bs[lcol + 2][lrow] = bv.z; Bs[lcol + 3][lrow] = bv.w;
        __syncthreads();
#pragma unroll
        for (int kk = 0; kk < 8; kk++) {
            float a[8], bb[8];
#pragma unroll
            for (int i = 0; i < 8; i++) a[i] = As[kk][ty * 8 + i];
#pragma unroll
            for (int j = 0; j < 8; j++) bb[j] = Bs[kk][tx * 8 + j];
#pragma unroll
            for (int i = 0; i < 8; i++)
#pragma unroll
                for (int j = 0; j < 8; j++) acc[i][j] = fmaf(a[i], bb[j], acc[i][j]);
        }
        __syncthreads();
    }

#pragma unroll
    for (int i = 0; i < 8; i++) {
        const int r = m0 + ty * 8 + i;
        const int t = r >> 2, b = r & 3;
#pragma unroll
        for (int j = 0; j < 8; j++) {
            const int n = n0 + tx * 8 + j;
            float v = acc[i][j] + bias[n];
            const int sec = n >> 9;
            const int e = n & 511;
            const int h = e >> 6, hd = e & 63;
            const int dst = ((b * cH + h) * cT + t) * cHD + hd;
            if (sec == 0)      g_q[dst] = v * 0.125f;
            else if (sec == 1) g_k[dst] = v;
            else               g_v[dst] = v;
        }
    }
}

// ---------------------------------------------------------------------------
// Kernel 2 (fused flash attention): per block = (h, q-tile of 128, b).
// S = Q K^T (+dist bias), online softmax, O += P V — no score tensor in gmem.
// Grid x = h (fastest) so the 8 heads sharing the same dist sectors run
// concurrently and hit L2.
// SMEM: Qs/Ks k-major [64][128], Vs [128][64], Ps transposed [s][row] with
// row-block XOR swizzle (blk = ty ^ (s>>3)) for conflict-free STS/LDS.128.
// ---------------------------------------------------------------------------
__global__ __launch_bounds__(256, 1) void k_attn(const float* __restrict__ dist) {
    extern __shared__ float sm[];
    float* Qs = sm;                       // [64][128]
    float* Ks = Qs + 64 * 128;            // [64][128]
    float* Vs = Ks + 64 * 128;            // [128][64]
    float* Ps = Vs + 128 * 64;            // [128][136]  (s-major, padded)

    const int h = blockIdx.x, mt = blockIdx.y, b = blockIdx.z;
    const int bh = b * cH + h;
    const int m0 = mt * 128;
    const int tid = threadIdx.x;
    const int tx = tid & 15, ty = tid >> 4;

    const float* Q = g_q + bh * cT * cHD;
    const float* K = g_k + bh * cT * cHD;
    const float* V = g_v + bh * cT * cHD;

    const int lrow = tid >> 1, lcol = (tid & 1) << 2;
    const int vrow = tid >> 1, vcol = (tid & 1) << 5;

    // Load Q tile transposed into Qs[k][row] (rows m0..m0+127)
#pragma unroll
    for (int k0 = 0; k0 < 64; k0 += 8) {
        float4 qv = *reinterpret_cast<const float4*>(Q + (m0 + lrow) * 64 + k0 + lcol);
        Qs[(k0 + lcol + 0) * 128 + lrow] = qv.x;
        Qs[(k0 + lcol + 1) * 128 + lrow] = qv.y;
        Qs[(k0 + lcol + 2) * 128 + lrow] = qv.z;
        Qs[(k0 + lcol + 3) * 128 + lrow] = qv.w;
    }

    float O[8][4];
    float mr[8], lr[8];
#pragma unroll
    for (int i = 0; i < 8; i++) {
        mr[i] = -1e30f; lr[i] = 0.f;
#pragma unroll
        for (int j = 0; j < 4; j++) O[i][j] = 0.f;
    }

    for (int s0 = 0; s0 < cT; s0 += 128) {
        // Load K tile transposed, V tile row-major
#pragma unroll
        for (int k0 = 0; k0 < 64; k0 += 8) {
            float4 kv = *reinterpret_cast<const float4*>(K + (s0 + lrow) * 64 + k0 + lcol);
            Ks[(k0 + lcol + 0) * 128 + lrow] = kv.x;
            Ks[(k0 + lcol + 1) * 128 + lrow] = kv.y;
            Ks[(k0 + lcol + 2) * 128 + lrow] = kv.z;
            Ks[(k0 + lcol + 3) * 128 + lrow] = kv.w;
        }
#pragma unroll
        for (int c = 0; c < 32; c += 4) {
            *reinterpret_cast<float4*>(Vs + vrow * 64 + vcol + c) =
                *reinterpret_cast<const float4*>(V + (s0 + vrow) * 64 + vcol + c);
        }
        __syncthreads();

        // S = Q K^T  (thread tile: rows ty*8+i, cols tx*8+j)
        float S[8][8];
#pragma unroll
        for (int i = 0; i < 8; i++)
#pragma unroll
            for (int j = 0; j < 8; j++) S[i][j] = 0.f;

        for (int kk = 0; kk < 64; kk++) {
            float4 a0 = *reinterpret_cast<const float4*>(Qs + kk * 128 + ty * 8);
            float4 a1 = *reinterpret_cast<const float4*>(Qs + kk * 128 + ty * 8 + 4);
            float4 b0 = *reinterpret_cast<const float4*>(Ks + kk * 128 + tx * 8);
            float4 b1 = *reinterpret_cast<const float4*>(Ks + kk * 128 + tx * 8 + 4);
            float a[8] = {a0.x, a0.y, a0.z, a0.w, a1.x, a1.y, a1.z, a1.w};
            float bb[8] = {b0.x, b0.y, b0.z, b0.w, b1.x, b1.y, b1.z, b1.w};
#pragma unroll
            for (int i = 0; i < 8; i++)
#pragma unroll
                for (int j = 0; j < 8; j++) S[i][j] = fmaf(a[i], bb[j], S[i][j]);
        }

        // + dist bias: dist[b, t, s, h], h innermost (one 32B sector per (t,s),
        // shared across the 8 concurrently-running head blocks via L2)
        const float* dbase = dist + (((size_t)b * cT + (m0 + ty * 8)) * cT + (s0 + tx * 8)) * cH + h;
#pragma unroll
        for (int i = 0; i < 8; i++) {
            const float* dp = dbase + (size_t)i * cT * cH;
#pragma unroll
            for (int j = 0; j < 8; j++)
                S[i][j] += __ldg(dp + j * cH);
        }

        // Online softmax per row (row owned by the 16 tx lanes of one ty group)
#pragma unroll
        for (int i = 0; i < 8; i++) {
            float rm = S[i][0];
#pragma unroll
            for (int j = 1; j < 8; j++) rm = fmaxf(rm, S[i][j]);
#pragma unroll
            for (int o = 8; o; o >>= 1) rm = fmaxf(rm, __shfl_xor_sync(0xffffffffu, rm, o));
            const float mn = fmaxf(mr[i], rm);
            const float scale = __expf(mr[i] - mn);
            mr[i] = mn;
            float sum = 0.f;
#pragma unroll
            for (int j = 0; j < 8; j++) { S[i][j] = __expf(S[i][j] - mn); sum += S[i][j]; }
#pragma unroll
            for (int o = 8; o; o >>= 1) sum += __shfl_xor_sync(0xffffffffu, sum, o);
            lr[i] = lr[i] * scale + sum;
#pragma unroll
            for (int j = 0; j < 4; j++) O[i][j] *= scale;
        }

        // Store P transposed: Ps[s][row], row-block swizzled by s>>3 (== writer tx)
#pragma unroll
        for (int j = 0; j < 8; j++) {
            const int s_loc = tx * 8 + j;
            float* base = Ps + s_loc * 136 + ((ty ^ tx) * 8);
            *reinterpret_cast<float4*>(base)     = make_float4(S[0][j], S[1][j], S[2][j], S[3][j]);
            *reinterpret_cast<float4*>(base + 4) = make_float4(S[4][j], S[5][j], S[6][j], S[7][j]);
        }
        __syncthreads();

        // O += P V   (thread tile: rows ty*8+i, hd cols tx*4+j)
        for (int s = 0; s < 128; s++) {
            const float* abase = Ps + s * 136 + ((ty ^ (s >> 3)) * 8);
            float4 a0 = *reinterpret_cast<const float4*>(abase);
            float4 a1 = *reinterpret_cast<const float4*>(abase + 4);
            float4 bv = *reinterpret_cast<const float4*>(Vs + s * 64 + tx * 4);
            float a[8] = {a0.x, a0.y, a0.z, a0.w, a1.x, a1.y, a1.z, a1.w};
            float bb[4] = {bv.x, bv.y, bv.z, bv.w};
#pragma unroll
            for (int i = 0; i < 8; i++)
#pragma unroll
                for (int j = 0; j < 4; j++) O[i][j] = fmaf(a[i], bb[j], O[i][j]);
        }
        __syncthreads();
    }

    // Normalize and write context in [T,B,E] layout
#pragma unroll
    for (int i = 0; i < 8; i++) {
        const float inv = 1.0f / lr[i];
        const int t = m0 + ty * 8 + i;
        float4 o = make_float4(O[i][0] * inv, O[i][1] * inv, O[i][2] * inv, O[i][3] * inv);
        *reinterpret_cast<float4*>(g_ctx + ((size_t)t * cB + b) * cE + h * cHD + tx * 4) = o;
    }
}

// ---------------------------------------------------------------------------
// Kernel 3: out-projection GEMM. M=4096, N=512, K=512 (NT), +bias -> d_out.
// ---------------------------------------------------------------------------
__global__ __launch_bounds__(256) void k_outproj(const float* __restrict__ W,
                                                 const float* __restrict__ bias,
                                                 float* __restrict__ out) {
    __shared__ float As[8][128];
    __shared__ float Bs[8][128];
    const int tid = threadIdx.x;
    const int tx = tid & 15, ty = tid >> 4;
    const int m0 = blockIdx.y * 128, n0 = blockIdx.x * 128;
    const int lrow = tid >> 1, lcol = (tid & 1) << 2;

    float acc[8][8];
#pragma unroll
    for (int i = 0; i < 8; i++)
#pragma unroll
        for (int j = 0; j < 8; j++) acc[i][j] = 0.f;

    const float* aptr = g_ctx + (m0 + lrow) * 512 + lcol;
    const float* bptr = W + (n0 + lrow) * 512 + lcol;

    for (int k0 = 0; k0 < 512; k0 += 8) {
        float4 av = *reinterpret_cast<const float4*>(aptr + k0);
        float4 bv = *reinterpret_cast<const float4*>(bptr + k0);
        As[lcol + 0][lrow] = av.x; As[lcol + 1][lrow] = av.y;
        As[lcol + 2][lrow] = av.z; As[lcol + 3][lrow] = av.w;
        Bs[lcol + 0][lrow] = bv.x; Bs[lcol + 1][lrow] = bv.y;
        Bs[lcol + 2][lrow] = bv.z; Bs[lcol + 3][lrow] = bv.w;
        __syncthreads();
#pragma unroll
        for (int kk = 0; kk < 8; kk++) {
            float a[8], bb[8];
#pragma unroll
            for (int i = 0; i < 8; i++) a[i] = As[kk][ty * 8 + i];
#pragma unroll
            for (int j = 0; j < 8; j++) bb[j] = Bs[kk][tx * 8 + j];
#pragma unroll
            for (int i = 0; i < 8; i++)
#pragma unroll
                for (int j = 0; j < 8; j++) acc[i][j] = fmaf(a[i], bb[j], acc[i][j]);
        }
        __syncthreads();
    }

#pragma unroll
    for (int i = 0; i < 8; i++) {
        const int r = m0 + ty * 8 + i;
#pragma unroll
        for (int j = 0; j < 8; j++) {
            const int n = n0 + tx * 8 + j;
            out[r * 512 + n] = acc[i][j] + bias[n];
        }
    }
}

// ---------------------------------------------------------------------------
extern "C" void kernel_launch(void* const* d_in, const int* in_sizes, int n_in,
                              void* d_out, int out_size) {
    const float* query = (const float*)d_in[0];
    const float* dist  = (const float*)d_in[1];
    const float* w_in  = (const float*)d_in[2];
    const float* b_in  = (const float*)d_in[3];
    const float* w_out = (const float*)d_in[4];
    const float* b_out = (const float*)d_in[5];
    float* out = (float*)d_out;

    // Dynamic smem for fused attention: Qs + Ks + Vs + Ps(padded 136)
    const int attn_smem = (64 * 128 + 64 * 128 + 128 * 64 + 128 * 136) * (int)sizeof(float);
    cudaFuncSetAttribute(k_attn, cudaFuncAttributeMaxDynamicSharedMemorySize, attn_smem);

    k_inproj <<<dim3(1536 / 128, 4096 / 128), 256>>>(query, w_in, b_in);
    k_attn   <<<dim3(cH, cT / 128, cB), 256, attn_smem>>>(dist);
    k_outproj<<<dim3(512 / 128, 4096 / 128), 256>>>(w_out, b_out, out);
}